// round 15
// baseline (speedup 1.0000x reference)
#include <cuda_runtime.h>
#include <cuda_fp16.h>
#include <cstdint>

#define N_NODES 100000
#define N_EDGES 1600000
#define NEG_SLOPE 0.2f
#define SCAN_BLOCKS 98  // ceil(100000/1024)
#define FLAGBIT (1 << 30)
#define GEMM_BLOCKS 782              // ceil(100000/128)
#define GEMM_THREADS (GEMM_BLOCKS * 256)
#define PADH 136   // halves per smem row (272B) -> conflict-free quad access

// ---------------- scratch (device globals; no allocation allowed) ----------------
// Self-restoring: globals needing zero at pipeline start are re-zeroed by a later
// stage of the SAME run (module load provides the initial zeros).
__device__ __half2 g_fth[N_NODES * 64]; // ft [N,128] fp16 (256B per node row)
__device__ float4 g_el4[N_NODES];        // el [N,4]
__device__ float4 g_er4[N_NODES];        // er [N,4]
__device__ int    g_cnt[N_NODES];        // in-degree histogram (agg re-zeroes)
__device__ int    g_off[N_NODES];        // CSR offsets; after scatter: segment END
__device__ int    g_srcs[N_EDGES];       // src node id, grouped by dst
__device__ float4 g_ez4[N_EDGES];        // per-edge exp(leakyrelu(score)) [4 heads]
__device__ int    g_flag[SCAN_BLOCKS];   // scan lookback flags (scatter re-zeroes)

// ---------------- K1: HMMA GEMM ft = feat @ W^T (+ el/er) + hidden histogram ----------------
// Block = 128 M-rows x 128 N-cols, K=128 resident in smem as fp16.
// 8 warps, each owns 16 rows x all 128 cols: 16 n-tiles of mma.m16n8k16 per
// k-step (8 k-steps). Epilogue head-aligned: el/er per-thread dots + quad shfls.
__global__ void __launch_bounds__(256)
gemm_el_er(const float* __restrict__ feat, const float* __restrict__ W,
           const float* __restrict__ attn_l, const float* __restrict__ attn_r,
           const int* __restrict__ dst) {
    extern __shared__ __half smemh[];
    __half* A_s = smemh;                  // [128][PADH]
    __half* B_s = smemh + 128 * PADH;     // [128][PADH]
    __shared__ float s_al[128], s_ar[128];

    const int tid = threadIdx.x;
    const int m0 = blockIdx.x * 128;

    // hidden histogram: grid-stride fire-and-forget REDs (g_cnt zeroed by prev run's agg)
    for (int e = blockIdx.x * 256 + tid; e < N_EDGES; e += GEMM_THREADS)
        atomicAdd(&g_cnt[__ldg(dst + e)], 1);

    if (tid < 128) { s_al[tid] = __ldg(attn_l + tid); s_ar[tid] = __ldg(attn_r + tid); }

    // fill smem: fp32 -> fp16 convert. 128 rows x 32 float4 = 4096 per matrix.
    for (int f = tid; f < 4096; f += 256) {
        int r = f >> 5, c = (f & 31) * 4;
        float4 v = make_float4(0.f, 0.f, 0.f, 0.f);
        int gm = m0 + r;
        if (gm < N_NODES) v = *(const float4*)(feat + gm * 128 + c);
        __half2 h0 = __floats2half2_rn(v.x, v.y), h1 = __floats2half2_rn(v.z, v.w);
        *(uint2*)(A_s + r * PADH + c) = make_uint2(*(uint32_t*)&h0, *(uint32_t*)&h1);
        float4 wv = *(const float4*)(W + r * 128 + c);
        __half2 w0 = __floats2half2_rn(wv.x, wv.y), w1 = __floats2half2_rn(wv.z, wv.w);
        *(uint2*)(B_s + r * PADH + c) = make_uint2(*(uint32_t*)&w0, *(uint32_t*)&w1);
    }
    __syncthreads();

    const int wid = tid >> 5, lane = tid & 31;
    const int g = lane >> 2, t = lane & 3;

    float acc[16][4];
#pragma unroll
    for (int j = 0; j < 16; j++)
#pragma unroll
        for (int q = 0; q < 4; q++) acc[j][q] = 0.f;

    const __half* arow0 = A_s + (wid * 16 + g) * PADH + 2 * t;
    const __half* arow1 = arow0 + 8 * PADH;

#pragma unroll
    for (int ks = 0; ks < 8; ks++) {
        const int k0 = ks * 16;
        uint32_t a0 = *(const uint32_t*)(arow0 + k0);
        uint32_t a1 = *(const uint32_t*)(arow1 + k0);
        uint32_t a2 = *(const uint32_t*)(arow0 + k0 + 8);
        uint32_t a3 = *(const uint32_t*)(arow1 + k0 + 8);
#pragma unroll
        for (int j = 0; j < 16; j++) {
            const __half* bp = B_s + (8 * j + g) * PADH + k0 + 2 * t;
            uint32_t b0 = *(const uint32_t*)(bp);
            uint32_t b1 = *(const uint32_t*)(bp + 8);
            asm volatile(
                "mma.sync.aligned.m16n8k16.row.col.f32.f16.f16.f32 "
                "{%0,%1,%2,%3}, {%4,%5,%6,%7}, {%8,%9}, {%0,%1,%2,%3};"
                : "+f"(acc[j][0]), "+f"(acc[j][1]), "+f"(acc[j][2]), "+f"(acc[j][3])
                : "r"(a0), "r"(a1), "r"(a2), "r"(a3), "r"(b0), "r"(b1));
        }
    }

    const int m = m0 + wid * 16 + g;
    float pl0[4] = {0.f, 0.f, 0.f, 0.f}, pl1[4] = {0.f, 0.f, 0.f, 0.f};
    float pr0[4] = {0.f, 0.f, 0.f, 0.f}, pr1[4] = {0.f, 0.f, 0.f, 0.f};
#pragma unroll
    for (int j = 0; j < 16; j++) {
        int col = 8 * j + 2 * t, h = j >> 2;
        float alx = s_al[col], aly = s_al[col + 1];
        float arx = s_ar[col], ary = s_ar[col + 1];
        pl0[h] = fmaf(acc[j][0], alx, fmaf(acc[j][1], aly, pl0[h]));
        pr0[h] = fmaf(acc[j][0], arx, fmaf(acc[j][1], ary, pr0[h]));
        pl1[h] = fmaf(acc[j][2], alx, fmaf(acc[j][3], aly, pl1[h]));
        pr1[h] = fmaf(acc[j][2], arx, fmaf(acc[j][3], ary, pr1[h]));
    }
#pragma unroll
    for (int h = 0; h < 4; h++) {
#pragma unroll
        for (int o = 1; o < 4; o <<= 1) {
            pl0[h] += __shfl_xor_sync(0xffffffffu, pl0[h], o);
            pl1[h] += __shfl_xor_sync(0xffffffffu, pl1[h], o);
            pr0[h] += __shfl_xor_sync(0xffffffffu, pr0[h], o);
            pr1[h] += __shfl_xor_sync(0xffffffffu, pr1[h], o);
        }
    }
    if (m < N_NODES) {
#pragma unroll
        for (int j = 0; j < 16; j++) {
            __half2 hh = __floats2half2_rn(acc[j][0], acc[j][1]);
            *(uint32_t*)((char*)g_fth + (size_t)m * 256 + (8 * j + 2 * t) * 2) = *(uint32_t*)&hh;
        }
        if (t == 0) {
            g_el4[m] = make_float4(pl0[0], pl0[1], pl0[2], pl0[3]);
            g_er4[m] = make_float4(pr0[0], pr0[1], pr0[2], pr0[3]);
        }
    }
    if (m + 8 < N_NODES) {
#pragma unroll
        for (int j = 0; j < 16; j++) {
            __half2 hh = __floats2half2_rn(acc[j][2], acc[j][3]);
            *(uint32_t*)((char*)g_fth + (size_t)(m + 8) * 256 + (8 * j + 2 * t) * 2) = *(uint32_t*)&hh;
        }
        if (t == 0) {
            g_el4[m + 8] = make_float4(pl1[0], pl1[1], pl1[2], pl1[3]);
            g_er4[m + 8] = make_float4(pr1[0], pr1[1], pr1[2], pr1[3]);
        }
    }
}

// ---------------- K2: exclusive scan (aggregate-only decoupled lookback) ----------------
__global__ void __launch_bounds__(1024, 1) scan_k() {
    __shared__ int warp_sums[32];
    __shared__ int s_prefix;
    const int bid = blockIdx.x, tid = threadIdx.x;
    const int lane = tid & 31, wid = tid >> 5;
    int idx = bid * 1024 + tid;
    int v = (idx < N_NODES) ? g_cnt[idx] : 0;
    int x = v;
#pragma unroll
    for (int o = 1; o < 32; o <<= 1) {
        int t = __shfl_up_sync(0xffffffffu, x, o);
        if (lane >= o) x += t;
    }
    if (lane == 31) warp_sums[wid] = x;
    __syncthreads();
    if (wid == 0) {
        int s = warp_sums[lane];
        int xs = s;
#pragma unroll
        for (int o = 1; o < 32; o <<= 1) {
            int t = __shfl_up_sync(0xffffffffu, xs, o);
            if (lane >= o) xs += t;
        }
        int tot = __shfl_sync(0xffffffffu, xs, 31);
        if (lane == 0) atomicExch(&g_flag[bid], tot | FLAGBIT);
        warp_sums[lane] = xs - s;
        int run = 0;
        for (int base = 0; base < bid; base += 32) {
            int j = base + lane;
            int val = 0;
            if (j < bid) {
                int f;
                do { f = atomicAdd(&g_flag[j], 0); } while (!(f & FLAGBIT));
                val = f & (FLAGBIT - 1);
            }
#pragma unroll
            for (int o = 16; o > 0; o >>= 1) val += __shfl_xor_sync(0xffffffffu, val, o);
            run += val;
        }
        if (lane == 0) s_prefix = run;
    }
    __syncthreads();
    if (idx < N_NODES) g_off[idx] = s_prefix + warp_sums[wid] + (x - v);
}

// ---------------- K3: scatter + edge score + exp ----------------
// Per edge: score = leakyrelu(el[src]+er[dst]) -> ez = exp(score) stored fp32 at
// the dst-grouped position. The random el/er gathers + MUFU exp ride the
// atomic-latency slack here instead of serializing agg's staging phase.
// Afterwards g_off[d] == segment end. Also re-zeroes g_flag.
__global__ void scatter_k(const int* __restrict__ src, const int* __restrict__ dst) {
    int e = blockIdx.x * blockDim.x + threadIdx.x;
    if (e < SCAN_BLOCKS) g_flag[e] = 0;
    if (e >= N_EDGES) return;
    int s = __ldg(src + e), d = __ldg(dst + e);
    float4 l = __ldg(&g_el4[s]);
    float4 r = __ldg(&g_er4[d]);
    float4 ev;
    ev.x = l.x + r.x; ev.y = l.y + r.y; ev.z = l.z + r.z; ev.w = l.w + r.w;
    ev.x = ev.x > 0.f ? ev.x : NEG_SLOPE * ev.x;
    ev.y = ev.y > 0.f ? ev.y : NEG_SLOPE * ev.y;
    ev.z = ev.z > 0.f ? ev.z : NEG_SLOPE * ev.z;
    ev.w = ev.w > 0.f ? ev.w : NEG_SLOPE * ev.w;
    int pos = atomicAdd(&g_off[d], 1);
    g_srcs[pos] = s;
    g_ez4[pos] = make_float4(__expf(ev.x), __expf(ev.y), __expf(ev.z), __expf(ev.w));
}

// ---------------- K4: fused softmax+aggregation ----------------
// One warp per dst node; segment = [g_off[w-1], g_off[w]).  Staging per 32-edge
// chunk is now two COALESCED loads (sn, ez4->smem); inner loop identical to the
// measured-best config: SHFL sn, LDS broadcast we, LDG.64 fp16 ft (256B/warp).
// Re-zeroes g_cnt.
__global__ void __launch_bounds__(256) agg_k(float* __restrict__ out) {
    __shared__ float4 s_we[8][32];
    const int w = (blockIdx.x * blockDim.x + threadIdx.x) >> 5;
    const int lane = threadIdx.x & 31;
    const int wid = (threadIdx.x >> 5) & 7;
    if (w >= N_NODES) return;
    const int s1 = g_off[w];
    const int s0 = (w == 0) ? 0 : g_off[w - 1];
    if (lane == 0) g_cnt[w] = 0;        // restore for next replay
    const int h = lane >> 3;

    const uint2* fp = (const uint2*)g_fth;

    float4 a = make_float4(0.f, 0.f, 0.f, 0.f);
    float s = 0.f;

    for (int base = s0; base < s1; base += 32) {
        const int cn = min(32, s1 - base);
        int sn_l = 0;
        if (lane < cn) {
            sn_l = __ldg(g_srcs + base + lane);          // coalesced
            s_we[wid][lane] = __ldg(&g_ez4[base + lane]); // coalesced 512B/warp
        }
        __syncwarp();
#pragma unroll 8
        for (int i = 0; i < cn; i++) {
            int sn = __shfl_sync(0xffffffffu, sn_l, i);
            float we = ((const float*)&s_we[wid][i])[h];     // LDS broadcast
            uint2 u = __ldg(fp + sn * 32 + lane);            // 256B/warp coalesced
            float2 f0 = __half22float2(*(__half2*)&u.x);
            float2 f1 = __half22float2(*(__half2*)&u.y);
            a.x = fmaf(f0.x, we, a.x);
            a.y = fmaf(f0.y, we, a.y);
            a.z = fmaf(f1.x, we, a.z);
            a.w = fmaf(f1.y, we, a.w);
            s += we;
        }
        __syncwarp();
    }
    float inv = (s1 > s0) ? 1.f / s : 0.f;
    ((float4*)out)[(size_t)w * 32 + lane] =
        make_float4(a.x * inv, a.y * inv, a.z * inv, a.w * inv);
}

// ---------------- launch (agg_k sits in profiled slot #4) ----------------
extern "C" void kernel_launch(void* const* d_in, const int* in_sizes, int n_in,
                              void* d_out, int out_size) {
    const float* feat   = (const float*)d_in[0];
    const float* W      = (const float*)d_in[1];
    const float* attn_l = (const float*)d_in[2];
    const float* attn_r = (const float*)d_in[3];
    const int*   src    = (const int*)d_in[4];
    const int*   dst    = (const int*)d_in[5];
    float* out = (float*)d_out;

    const int smem = 2 * 128 * PADH * (int)sizeof(__half);   // 69,632 B
    cudaFuncSetAttribute(gemm_el_er, cudaFuncAttributeMaxDynamicSharedMemorySize, smem);
    gemm_el_er<<<GEMM_BLOCKS, 256, smem>>>(feat, W, attn_l, attn_r, dst);
    scan_k    <<<SCAN_BLOCKS, 1024>>>();
    scatter_k <<<(N_EDGES + 255) / 256, 256>>>(src, dst);
    agg_k     <<<(N_NODES * 32 + 255) / 256, 256>>>(out);
}

// round 17
// speedup vs baseline: 1.1586x; 1.1586x over previous
#include <cuda_runtime.h>
#include <cuda_fp16.h>
#include <cstdint>

#define N_NODES 100000
#define N_EDGES 1600000
#define NEG_SLOPE 0.2f
#define SCAN_BLOCKS 98  // ceil(100000/1024)
#define FLAGBIT (1 << 30)
#define GEMM_BLOCKS 782              // ceil(100000/128)
#define GEMM_THREADS (GEMM_BLOCKS * 256)
#define PADH 136   // halves per smem row (272B) -> conflict-free quad access

// ---------------- scratch (device globals; no allocation allowed) ----------------
// Self-restoring: globals needing zero at pipeline start are re-zeroed by a later
// stage of the SAME run (module load provides the initial zeros).
__device__ __half2 g_fth[N_NODES * 64]; // ft [N,128] fp16 (256B per node row)
__device__ float4 g_el4[N_NODES];        // el [N,4]
__device__ float4 g_er4[N_NODES];        // er [N,4]
__device__ int    g_cnt[N_NODES];        // in-degree histogram (agg re-zeroes)
__device__ int    g_off[N_NODES];        // CSR offsets; after scatter: segment END
__device__ int    g_srcs[N_EDGES];       // src node id, grouped by dst
__device__ int    g_flag[SCAN_BLOCKS];   // scan lookback flags (scatter re-zeroes)

// ---------------- K1: HMMA GEMM ft = feat @ W^T (+ el/er) + hidden histogram ----------------
// Block = 128 M-rows x 128 N-cols, K=128 resident in smem as fp16.
// 8 warps, each owns 16 rows x all 128 cols: 16 n-tiles of mma.m16n8k16 per
// k-step (8 k-steps). __launch_bounds__(256,2) forces 2 resident blocks/SM so
// one block's fill overlaps the other's MMA/epilogue.
__global__ void __launch_bounds__(256, 2)
gemm_el_er(const float* __restrict__ feat, const float* __restrict__ W,
           const float* __restrict__ attn_l, const float* __restrict__ attn_r,
           const int* __restrict__ dst) {
    extern __shared__ __half smemh[];
    __half* A_s = smemh;                  // [128][PADH]
    __half* B_s = smemh + 128 * PADH;     // [128][PADH]
    __shared__ float s_al[128], s_ar[128];

    const int tid = threadIdx.x;
    const int m0 = blockIdx.x * 128;

    // hidden histogram: grid-stride fire-and-forget REDs (g_cnt zeroed by prev run's agg)
    for (int e = blockIdx.x * 256 + tid; e < N_EDGES; e += GEMM_THREADS)
        atomicAdd(&g_cnt[__ldg(dst + e)], 1);

    if (tid < 128) { s_al[tid] = __ldg(attn_l + tid); s_ar[tid] = __ldg(attn_r + tid); }

    // fill smem: fp32 -> fp16 convert. 128 rows x 32 float4 = 4096 per matrix.
    for (int f = tid; f < 4096; f += 256) {
        int r = f >> 5, c = (f & 31) * 4;
        float4 v = make_float4(0.f, 0.f, 0.f, 0.f);
        int gm = m0 + r;
        if (gm < N_NODES) v = *(const float4*)(feat + gm * 128 + c);
        __half2 h0 = __floats2half2_rn(v.x, v.y), h1 = __floats2half2_rn(v.z, v.w);
        *(uint2*)(A_s + r * PADH + c) = make_uint2(*(uint32_t*)&h0, *(uint32_t*)&h1);
        float4 wv = *(const float4*)(W + r * 128 + c);
        __half2 w0 = __floats2half2_rn(wv.x, wv.y), w1 = __floats2half2_rn(wv.z, wv.w);
        *(uint2*)(B_s + r * PADH + c) = make_uint2(*(uint32_t*)&w0, *(uint32_t*)&w1);
    }
    __syncthreads();

    const int wid = tid >> 5, lane = tid & 31;
    const int g = lane >> 2, t = lane & 3;

    float acc[16][4];
#pragma unroll
    for (int j = 0; j < 16; j++)
#pragma unroll
        for (int q = 0; q < 4; q++) acc[j][q] = 0.f;

    const __half* arow0 = A_s + (wid * 16 + g) * PADH + 2 * t;
    const __half* arow1 = arow0 + 8 * PADH;

#pragma unroll
    for (int ks = 0; ks < 8; ks++) {
        const int k0 = ks * 16;
        uint32_t a0 = *(const uint32_t*)(arow0 + k0);
        uint32_t a1 = *(const uint32_t*)(arow1 + k0);
        uint32_t a2 = *(const uint32_t*)(arow0 + k0 + 8);
        uint32_t a3 = *(const uint32_t*)(arow1 + k0 + 8);
#pragma unroll
        for (int j = 0; j < 16; j++) {
            const __half* bp = B_s + (8 * j + g) * PADH + k0 + 2 * t;
            uint32_t b0 = *(const uint32_t*)(bp);
            uint32_t b1 = *(const uint32_t*)(bp + 8);
            asm volatile(
                "mma.sync.aligned.m16n8k16.row.col.f32.f16.f16.f32 "
                "{%0,%1,%2,%3}, {%4,%5,%6,%7}, {%8,%9}, {%0,%1,%2,%3};"
                : "+f"(acc[j][0]), "+f"(acc[j][1]), "+f"(acc[j][2]), "+f"(acc[j][3])
                : "r"(a0), "r"(a1), "r"(a2), "r"(a3), "r"(b0), "r"(b1));
        }
    }

    // epilogue: thread owns rows (m, m+8), cols {8j+2t, 8j+2t+1}; head h = j>>2
    const int m = m0 + wid * 16 + g;
    float pl0[4] = {0.f, 0.f, 0.f, 0.f}, pl1[4] = {0.f, 0.f, 0.f, 0.f};
    float pr0[4] = {0.f, 0.f, 0.f, 0.f}, pr1[4] = {0.f, 0.f, 0.f, 0.f};
#pragma unroll
    for (int j = 0; j < 16; j++) {
        int col = 8 * j + 2 * t, h = j >> 2;
        float alx = s_al[col], aly = s_al[col + 1];
        float arx = s_ar[col], ary = s_ar[col + 1];
        pl0[h] = fmaf(acc[j][0], alx, fmaf(acc[j][1], aly, pl0[h]));
        pr0[h] = fmaf(acc[j][0], arx, fmaf(acc[j][1], ary, pr0[h]));
        pl1[h] = fmaf(acc[j][2], alx, fmaf(acc[j][3], aly, pl1[h]));
        pr1[h] = fmaf(acc[j][2], arx, fmaf(acc[j][3], ary, pr1[h]));
    }
#pragma unroll
    for (int h = 0; h < 4; h++) {
#pragma unroll
        for (int o = 1; o < 4; o <<= 1) {
            pl0[h] += __shfl_xor_sync(0xffffffffu, pl0[h], o);
            pl1[h] += __shfl_xor_sync(0xffffffffu, pl1[h], o);
            pr0[h] += __shfl_xor_sync(0xffffffffu, pr0[h], o);
            pr1[h] += __shfl_xor_sync(0xffffffffu, pr1[h], o);
        }
    }
    if (m < N_NODES) {
#pragma unroll
        for (int j = 0; j < 16; j++) {
            __half2 hh = __floats2half2_rn(acc[j][0], acc[j][1]);
            *(uint32_t*)((char*)g_fth + (size_t)m * 256 + (8 * j + 2 * t) * 2) = *(uint32_t*)&hh;
        }
        if (t == 0) {
            g_el4[m] = make_float4(pl0[0], pl0[1], pl0[2], pl0[3]);
            g_er4[m] = make_float4(pr0[0], pr0[1], pr0[2], pr0[3]);
        }
    }
    if (m + 8 < N_NODES) {
#pragma unroll
        for (int j = 0; j < 16; j++) {
            __half2 hh = __floats2half2_rn(acc[j][2], acc[j][3]);
            *(uint32_t*)((char*)g_fth + (size_t)(m + 8) * 256 + (8 * j + 2 * t) * 2) = *(uint32_t*)&hh;
        }
        if (t == 0) {
            g_el4[m + 8] = make_float4(pl1[0], pl1[1], pl1[2], pl1[3]);
            g_er4[m + 8] = make_float4(pr1[0], pr1[1], pr1[2], pr1[3]);
        }
    }
}

// ---------------- K2: exclusive scan (aggregate-only decoupled lookback) ----------------
__global__ void __launch_bounds__(1024, 1) scan_k() {
    __shared__ int warp_sums[32];
    __shared__ int s_prefix;
    const int bid = blockIdx.x, tid = threadIdx.x;
    const int lane = tid & 31, wid = tid >> 5;
    int idx = bid * 1024 + tid;
    int v = (idx < N_NODES) ? g_cnt[idx] : 0;
    int x = v;
#pragma unroll
    for (int o = 1; o < 32; o <<= 1) {
        int t = __shfl_up_sync(0xffffffffu, x, o);
        if (lane >= o) x += t;
    }
    if (lane == 31) warp_sums[wid] = x;
    __syncthreads();
    if (wid == 0) {
        int s = warp_sums[lane];
        int xs = s;
#pragma unroll
        for (int o = 1; o < 32; o <<= 1) {
            int t = __shfl_up_sync(0xffffffffu, xs, o);
            if (lane >= o) xs += t;
        }
        int tot = __shfl_sync(0xffffffffu, xs, 31);
        if (lane == 0) atomicExch(&g_flag[bid], tot | FLAGBIT);
        warp_sums[lane] = xs - s;
        int run = 0;
        for (int base = 0; base < bid; base += 32) {
            int j = base + lane;
            int val = 0;
            if (j < bid) {
                int f;
                do { f = atomicAdd(&g_flag[j], 0); } while (!(f & FLAGBIT));
                val = f & (FLAGBIT - 1);
            }
#pragma unroll
            for (int o = 16; o > 0; o >>= 1) val += __shfl_xor_sync(0xffffffffu, val, o);
            run += val;
        }
        if (lane == 0) s_prefix = run;
    }
    __syncthreads();
    if (idx < N_NODES) g_off[idx] = s_prefix + warp_sums[wid] + (x - v);
}

// ---------------- K3: scatter edge src ids into dst-grouped order ----------------
__global__ void scatter_k(const int* __restrict__ src, const int* __restrict__ dst) {
    int e = blockIdx.x * blockDim.x + threadIdx.x;
    if (e < SCAN_BLOCKS) g_flag[e] = 0;
    if (e >= N_EDGES) return;
    int pos = atomicAdd(&g_off[__ldg(dst + e)], 1);
    g_srcs[pos] = __ldg(src + e);
}

// ---------------- K4: fused score+exp+softmax+aggregation (measured-best config) ----------------
__global__ void __launch_bounds__(256) agg_k(float* __restrict__ out) {
    __shared__ float4 s_we[8][32];
    const int w = (blockIdx.x * blockDim.x + threadIdx.x) >> 5;
    const int lane = threadIdx.x & 31;
    const int wid = (threadIdx.x >> 5) & 7;
    if (w >= N_NODES) return;
    const int s1 = g_off[w];
    const int s0 = (w == 0) ? 0 : g_off[w - 1];
    if (lane == 0) g_cnt[w] = 0;        // restore for next replay
    const int h = lane >> 3;

    const float4 er4 = __ldg(&g_er4[w]);
    const uint2* fp = (const uint2*)g_fth;

    float4 a = make_float4(0.f, 0.f, 0.f, 0.f);
    float s = 0.f;

    for (int base = s0; base < s1; base += 32) {
        const int cn = min(32, s1 - base);
        int sn_l = 0;
        if (lane < cn) {
            sn_l = __ldg(g_srcs + base + lane);
            float4 el = __ldg(&g_el4[sn_l]);
            float4 ev;
            ev.x = el.x + er4.x; ev.y = el.y + er4.y;
            ev.z = el.z + er4.z; ev.w = el.w + er4.w;
            ev.x = ev.x > 0.f ? ev.x : NEG_SLOPE * ev.x;
            ev.y = ev.y > 0.f ? ev.y : NEG_SLOPE * ev.y;
            ev.z = ev.z > 0.f ? ev.z : NEG_SLOPE * ev.z;
            ev.w = ev.w > 0.f ? ev.w : NEG_SLOPE * ev.w;
            s_we[wid][lane] = make_float4(__expf(ev.x), __expf(ev.y),
                                          __expf(ev.z), __expf(ev.w));
        }
        __syncwarp();
#pragma unroll 8
        for (int i = 0; i < cn; i++) {
            int sn = __shfl_sync(0xffffffffu, sn_l, i);
            float we = ((const float*)&s_we[wid][i])[h];     // LDS broadcast
            uint2 u = __ldg(fp + sn * 32 + lane);            // 256B/warp coalesced
            float2 f0 = __half22float2(*(__half2*)&u.x);
            float2 f1 = __half22float2(*(__half2*)&u.y);
            a.x = fmaf(f0.x, we, a.x);
            a.y = fmaf(f0.y, we, a.y);
            a.z = fmaf(f1.x, we, a.z);
            a.w = fmaf(f1.y, we, a.w);
            s += we;
        }
        __syncwarp();
    }
    float inv = (s1 > s0) ? 1.f / s : 0.f;
    ((float4*)out)[(size_t)w * 32 + lane] =
        make_float4(a.x * inv, a.y * inv, a.z * inv, a.w * inv);
}

// ---------------- launch (agg_k sits in profiled slot #4) ----------------
extern "C" void kernel_launch(void* const* d_in, const int* in_sizes, int n_in,
                              void* d_out, int out_size) {
    const float* feat   = (const float*)d_in[0];
    const float* W      = (const float*)d_in[1];
    const float* attn_l = (const float*)d_in[2];
    const float* attn_r = (const float*)d_in[3];
    const int*   src    = (const int*)d_in[4];
    const int*   dst    = (const int*)d_in[5];
    float* out = (float*)d_out;

    const int smem = 2 * 128 * PADH * (int)sizeof(__half);   // 69,632 B
    cudaFuncSetAttribute(gemm_el_er, cudaFuncAttributeMaxDynamicSharedMemorySize, smem);
    gemm_el_er<<<GEMM_BLOCKS, 256, smem>>>(feat, W, attn_l, attn_r, dst);
    scan_k    <<<SCAN_BLOCKS, 1024>>>();
    scatter_k <<<(N_EDGES + 255) / 256, 256>>>(src, dst);
    agg_k     <<<(N_NODES * 32 + 255) / 256, 256>>>(out);
}